// round 6
// baseline (speedup 1.0000x reference)
#include <cuda_runtime.h>
#include <math.h>

#define PI_F 3.14159265358979323846f

static const int B = 32, C = 4, H = 512, W = 512;
static const int WSM = 512;     // floats of staging smem per warp (2KB)

__device__ __forceinline__ float clampf_(float v, float lo, float hi) {
    return fminf(fmaxf(v, lo), hi);
}

// ---------------------------------------------------------------------------
// Fused kernel, per-WARP smem-staged bilinear sampling (channel-serial):
//  - per-thread recompute of fwd/inv affine matrices from fc2 (fp32)
//  - grid/inv_grid float2 writes; mat/inv_mat from one block
//  - each warp computes its 8x4 tile's source window from the 4 corner
//    preimages (exact same FP expressions as per-pixel -> provable bounds),
//    stages it once per channel into a private 2KB smem slot with coalesced
//    row loads, then takes the 4 bilinear taps as LDS. Warp-uniform fallback
//    to direct gathers when the window exceeds the slot.
// Warp tile: 8 wide x 4 tall; block tile 32x8.
// ---------------------------------------------------------------------------
__global__ __launch_bounds__(256)
void fused_affine_kernel(const float* __restrict__ src,
                         const float* __restrict__ fc2,
                         float* __restrict__ out_trans,
                         float* __restrict__ out_mat,
                         float* __restrict__ out_inv,
                         float* __restrict__ out_grid,
                         float* __restrict__ out_invgrid) {
    __shared__ float sm[8 * WSM];   // 16KB: one 512-float slot per warp

    const int b = blockIdx.z;

    // --- rebuild matrices in registers (uniform across block) ---
    const float* __restrict__ f = fc2 + b * 7;
    float f0 = __ldg(&f[0]), f1 = __ldg(&f[1]), f2 = __ldg(&f[2]);
    float f3 = __ldg(&f[3]), f4 = __ldg(&f[4]), f5 = __ldg(&f[5]);
    float f6 = __ldg(&f[6]);

    const float theta = clampf_(f0 * 0.3f, -1.f, 1.f) * PI_F;
    const float sx = clampf_(f1 * 0.3f + 1.0f, 0.f, 5.f);
    const float sy = clampf_(f2 * 0.3f + 1.0f, 0.f, 5.f);
    const float tx = f3 * 0.3f;
    const float ty = f4 * 0.3f;
    const float shxy = clampf_(f5 * 0.3f, -1.f, 1.f) * PI_F;
    const float shyx = clampf_(f6 * 0.3f, -1.f, 1.f) * PI_F;

    const float c = cosf(theta), s = sinf(theta);
    const float a  = fmaf(shxy * sy, s, sx * c);
    const float bb = fmaf(shxy * sy, c, -sx * s);
    const float d  = fmaf(shyx * sx, c, sy * s);
    const float e  = fmaf(-shyx * sx, s, sy * c);

    const float det = fmaf(a, e, -bb * d);
    const float rdet = 1.0f / det;
    const float ia  = e * rdet;
    const float ib  = -bb * rdet;
    const float itx = fmaf(bb, ty, -e * tx) * rdet;
    const float id  = -d * rdet;
    const float ie  = a * rdet;
    const float ity = fmaf(d, tx, -a * ty) * rdet;

    if (blockIdx.x == 0 && blockIdx.y == 0 && threadIdx.x == 0) {
        float* om = out_mat + b * 9;
        om[0] = a;  om[1] = bb; om[2] = tx;
        om[3] = d;  om[4] = e;  om[5] = ty;
        om[6] = 0.f; om[7] = 0.f; om[8] = 1.f;
        float* oi = out_inv + b * 9;
        oi[0] = ia; oi[1] = ib; oi[2] = itx;
        oi[3] = id; oi[4] = ie; oi[5] = ity;
        oi[6] = 0.f; oi[7] = 0.f; oi[8] = 1.f;
    }

    // --- pixel coordinates: 8x4 warp tile, 32x8 block tile ---
    const int tid = threadIdx.x;
    const int lane = tid & 31;
    const int warp = tid >> 5;
    const int lx = lane & 7;
    const int ly = lane >> 3;
    const int wx = warp & 3;
    const int wy = warp >> 2;

    const int W0 = blockIdx.x * 32;
    const int H0 = blockIdx.y * 8;
    const int wtx0 = W0 + wx * 8;     // warp tile origin
    const int wty0 = H0 + wy * 4;
    const int w = wtx0 + lx;
    const int h = wty0 + ly;
    const int pix = h * W + w;

    const float x = (2.0f * (float)w + 1.0f) * (1.0f / (float)W) - 1.0f;
    const float y = (2.0f * (float)h + 1.0f) * (1.0f / (float)H) - 1.0f;

    const float gx = fmaf(a, x, fmaf(bb, y, tx));
    const float gy = fmaf(d, x, fmaf(e, y, ty));
    const float igx = fmaf(ia, x, fmaf(ib, y, itx));
    const float igy = fmaf(id, x, fmaf(ie, y, ity));

    const size_t gidx = (size_t)b * (H * W) + (size_t)pix;
    reinterpret_cast<float2*>(out_grid)[gidx]    = make_float2(gx, gy);
    reinterpret_cast<float2*>(out_invgrid)[gidx] = make_float2(igx, igy);

    // --- bilinear taps ---
    const float ixf = ((gx + 1.0f) * (float)W - 1.0f) * 0.5f;
    const float iyf = ((gy + 1.0f) * (float)H - 1.0f) * 0.5f;
    const float x0f = floorf(ixf);
    const float y0f = floorf(iyf);
    const float wxf = ixf - x0f;
    const float wyf = iyf - y0f;
    const int x0 = (int)x0f;
    const int y0 = (int)y0f;
    const int x1 = x0 + 1;
    const int y1 = y0 + 1;

    const float vx0 = (x0 >= 0 && x0 < W) ? 1.0f : 0.0f;
    const float vx1 = (x1 >= 0 && x1 < W) ? 1.0f : 0.0f;
    const float vy0 = (y0 >= 0 && y0 < H) ? 1.0f : 0.0f;
    const float vy1 = (y1 >= 0 && y1 < H) ? 1.0f : 0.0f;

    const int cx0 = min(max(x0, 0), W - 1);
    const int cx1 = min(max(x1, 0), W - 1);
    const int cy0 = min(max(y0, 0), H - 1);
    const int cy1 = min(max(y1, 0), H - 1);

    const float w00 = (1.0f - wxf) * (1.0f - wyf) * vx0 * vy0;
    const float w01 = wxf * (1.0f - wyf) * vx1 * vy0;
    const float w10 = (1.0f - wxf) * wyf * vx0 * vy1;
    const float w11 = wxf * wyf * vx1 * vy1;

    const float* __restrict__ sb = src + (size_t)b * C * H * W;
    float* __restrict__ ob = out_trans + (size_t)b * C * H * W;

    // --- warp-uniform source window from the 4 warp-tile corner preimages ---
    // identical FP expressions as the per-pixel path => exact bounds (fmaf is
    // monotone per argument; affine extremes are at corners).
    #define PIX_IX(WW, HH) \
        ((fmaf(a, (2.0f * (float)(WW) + 1.0f) * (1.0f / (float)W) - 1.0f, \
               fmaf(bb, (2.0f * (float)(HH) + 1.0f) * (1.0f / (float)H) - 1.0f, tx)) \
          + 1.0f) * (float)W - 1.0f) * 0.5f
    #define PIX_IY(WW, HH) \
        ((fmaf(d, (2.0f * (float)(WW) + 1.0f) * (1.0f / (float)W) - 1.0f, \
               fmaf(e, (2.0f * (float)(HH) + 1.0f) * (1.0f / (float)H) - 1.0f, ty)) \
          + 1.0f) * (float)H - 1.0f) * 0.5f

    const float cxa = PIX_IX(wtx0, wty0),     cya = PIX_IY(wtx0, wty0);
    const float cxb = PIX_IX(wtx0 + 7, wty0), cyb = PIX_IY(wtx0 + 7, wty0);
    const float cxc = PIX_IX(wtx0, wty0 + 3), cyc = PIX_IY(wtx0, wty0 + 3);
    const float cxd = PIX_IX(wtx0 + 7, wty0 + 3), cyd = PIX_IY(wtx0 + 7, wty0 + 3);
    #undef PIX_IX
    #undef PIX_IY

    const float pxmin = fminf(fminf(cxa, cxb), fminf(cxc, cxd));
    const float pxmax = fmaxf(fmaxf(cxa, cxb), fmaxf(cxc, cxd));
    const float pymin = fminf(fminf(cya, cyb), fminf(cyc, cyd));
    const float pymax = fmaxf(fmaxf(cya, cyb), fmaxf(cyc, cyd));

    const int xmin = min(max((int)floorf(pxmin), 0), W - 1);
    const int xmax = min(max((int)floorf(pxmax) + 1, 0), W - 1);
    const int ymin = min(max((int)floorf(pymin), 0), H - 1);
    const int ymax = min(max((int)floorf(pymax) + 1, 0), H - 1);

    const int xs = xmax - xmin + 1;
    const int ys = ymax - ymin + 1;
    const int pitch = xs | 1;                 // odd pitch spreads LDS banks

    if (ys * pitch <= WSM) {
        // ---------------- per-warp staged path ----------------
        float* __restrict__ wsm = sm + warp * WSM;
        const int ox0 = cx0 - xmin;
        const int ox1 = cx1 - xmin;
        const int oy0 = (cy0 - ymin) * pitch;
        const int oy1 = (cy1 - ymin) * pitch;

#pragma unroll
        for (int ch = 0; ch < C; ch++) {
            const float* __restrict__ img = sb + (size_t)ch * (H * W);
            __syncwarp();                      // drain prior-channel reads
            for (int r = 0; r < ys; r++) {
                const float* __restrict__ srow = img + (ymin + r) * W + xmin;
                float* __restrict__ drow = wsm + r * pitch;
                for (int xx = lane; xx < xs; xx += 32)
                    drow[xx] = __ldg(&srow[xx]);
            }
            __syncwarp();

            const float v00 = wsm[oy0 + ox0];
            const float v01 = wsm[oy0 + ox1];
            const float v10 = wsm[oy1 + ox0];
            const float v11 = wsm[oy1 + ox1];
            const float r = fmaf(v00, w00, fmaf(v01, w01, fmaf(v10, w10, v11 * w11)));
            ob[(size_t)ch * (H * W) + pix] = r;
        }
    } else {
        // ---------------- direct-gather fallback (R3 path) ----------------
        const int off00 = cy0 * W + cx0;
        const int off01 = cy0 * W + cx1;
        const int off10 = cy1 * W + cx0;
        const int off11 = cy1 * W + cx1;

#pragma unroll
        for (int ch = 0; ch < C; ch++) {
            const float* __restrict__ img = sb + (size_t)ch * (H * W);
            float v00 = __ldg(&img[off00]);
            float v01 = __ldg(&img[off01]);
            float v10 = __ldg(&img[off10]);
            float v11 = __ldg(&img[off11]);
            float r = fmaf(v00, w00, fmaf(v01, w01, fmaf(v10, w10, v11 * w11)));
            ob[(size_t)ch * (H * W) + pix] = r;
        }
    }
}

extern "C" void kernel_launch(void* const* d_in, const int* in_sizes, int n_in,
                              void* d_out, int out_size) {
    const float* src = (const float*)d_in[0];
    const float* fc2 = (const float*)d_in[1];
    float* out = (float*)d_out;

    // output layout: transformed | mat | inv_mat | grid | inv_grid
    const size_t n_trans = (size_t)B * C * H * W;          // 33,554,432
    const size_t n_mat = (size_t)B * 9;                    // 288
    const size_t n_grid = (size_t)B * H * W * 2;           // 16,777,216

    float* out_trans = out;
    float* out_mat   = out + n_trans;
    float* out_inv   = out_mat + n_mat;
    float* out_grid  = out_inv + n_mat;
    float* out_igrid = out_grid + n_grid;

    dim3 grid(W / 32, H / 8, B);
    fused_affine_kernel<<<grid, 256>>>(src, fc2, out_trans, out_mat, out_inv,
                                       out_grid, out_igrid);
}

// round 7
// speedup vs baseline: 3.5068x; 3.5068x over previous
#include <cuda_runtime.h>
#include <math.h>

#define PI_F 3.14159265358979323846f

static const int B = 32, C = 4, H = 512, W = 512;

__device__ __forceinline__ float clampf_(float v, float lo, float hi) {
    return fminf(fmaxf(v, lo), hi);
}

// ---------------------------------------------------------------------------
// Fused kernel (R3 skeleton) with paired-tap LDG.64 gathers:
//  - per-thread recompute of fwd/inv affine matrices from fc2 (fp32)
//  - grid/inv_grid float2 streaming stores; mat/inv_mat from one block
//  - bilinear sample: per source row, one aligned float2 A covers v_left
//    always and v_right for even-cx0 lanes; a lane-predicated float2 B covers
//    the rest. Cuts gather sector-touches ~20% vs 4 scalar gathers.
// Warp tile: 8 wide x 4 tall; block tile 32x8.
// ---------------------------------------------------------------------------
__global__ __launch_bounds__(256)
void fused_affine_kernel(const float* __restrict__ src,
                         const float* __restrict__ fc2,
                         float* __restrict__ out_trans,
                         float* __restrict__ out_mat,
                         float* __restrict__ out_inv,
                         float* __restrict__ out_grid,
                         float* __restrict__ out_invgrid) {
    const int b = blockIdx.z;

    // --- rebuild matrices in registers (uniform across block) ---
    const float* __restrict__ f = fc2 + b * 7;
    float f0 = __ldg(&f[0]), f1 = __ldg(&f[1]), f2 = __ldg(&f[2]);
    float f3 = __ldg(&f[3]), f4 = __ldg(&f[4]), f5 = __ldg(&f[5]);
    float f6 = __ldg(&f[6]);

    const float theta = clampf_(f0 * 0.3f, -1.f, 1.f) * PI_F;
    const float sx = clampf_(f1 * 0.3f + 1.0f, 0.f, 5.f);
    const float sy = clampf_(f2 * 0.3f + 1.0f, 0.f, 5.f);
    const float tx = f3 * 0.3f;
    const float ty = f4 * 0.3f;
    const float shxy = clampf_(f5 * 0.3f, -1.f, 1.f) * PI_F;
    const float shyx = clampf_(f6 * 0.3f, -1.f, 1.f) * PI_F;

    const float c = cosf(theta), s = sinf(theta);
    const float a  = fmaf(shxy * sy, s, sx * c);
    const float bb = fmaf(shxy * sy, c, -sx * s);
    const float d  = fmaf(shyx * sx, c, sy * s);
    const float e  = fmaf(-shyx * sx, s, sy * c);

    const float det = fmaf(a, e, -bb * d);
    const float rdet = 1.0f / det;
    const float ia  = e * rdet;
    const float ib  = -bb * rdet;
    const float itx = fmaf(bb, ty, -e * tx) * rdet;
    const float id  = -d * rdet;
    const float ie  = a * rdet;
    const float ity = fmaf(d, tx, -a * ty) * rdet;

    if (blockIdx.x == 0 && blockIdx.y == 0 && threadIdx.x == 0) {
        float* om = out_mat + b * 9;
        om[0] = a;  om[1] = bb; om[2] = tx;
        om[3] = d;  om[4] = e;  om[5] = ty;
        om[6] = 0.f; om[7] = 0.f; om[8] = 1.f;
        float* oi = out_inv + b * 9;
        oi[0] = ia; oi[1] = ib; oi[2] = itx;
        oi[3] = id; oi[4] = ie; oi[5] = ity;
        oi[6] = 0.f; oi[7] = 0.f; oi[8] = 1.f;
    }

    // --- pixel coordinates: 8x4 warp tile, 32x8 block tile ---
    const int tid = threadIdx.x;
    const int lane = tid & 31;
    const int warp = tid >> 5;
    const int lx = lane & 7;
    const int ly = lane >> 3;
    const int wx = warp & 3;
    const int wy = warp >> 2;

    const int w = blockIdx.x * 32 + wx * 8 + lx;
    const int h = blockIdx.y * 8 + wy * 4 + ly;
    const int pix = h * W + w;

    const float x = (2.0f * (float)w + 1.0f) * (1.0f / (float)W) - 1.0f;
    const float y = (2.0f * (float)h + 1.0f) * (1.0f / (float)H) - 1.0f;

    const float gx = fmaf(a, x, fmaf(bb, y, tx));
    const float gy = fmaf(d, x, fmaf(e, y, ty));
    const float igx = fmaf(ia, x, fmaf(ib, y, itx));
    const float igy = fmaf(id, x, fmaf(ie, y, ity));

    const size_t gidx = (size_t)b * (H * W) + (size_t)pix;
    __stcs(reinterpret_cast<float2*>(out_grid) + gidx,    make_float2(gx, gy));
    __stcs(reinterpret_cast<float2*>(out_invgrid) + gidx, make_float2(igx, igy));

    // --- bilinear taps ---
    const float ixf = ((gx + 1.0f) * (float)W - 1.0f) * 0.5f;
    const float iyf = ((gy + 1.0f) * (float)H - 1.0f) * 0.5f;
    const float x0f = floorf(ixf);
    const float y0f = floorf(iyf);
    const float wxf = ixf - x0f;
    const float wyf = iyf - y0f;
    const int x0 = (int)x0f;
    const int y0 = (int)y0f;
    const int x1 = x0 + 1;
    const int y1 = y0 + 1;

    const float vx0 = (x0 >= 0 && x0 < W) ? 1.0f : 0.0f;
    const float vx1 = (x1 >= 0 && x1 < W) ? 1.0f : 0.0f;
    const float vy0 = (y0 >= 0 && y0 < H) ? 1.0f : 0.0f;
    const float vy1 = (y1 >= 0 && y1 < H) ? 1.0f : 0.0f;

    const int cx0 = min(max(x0, 0), W - 1);
    const int cx1 = min(max(x1, 0), W - 1);
    const int cy0 = min(max(y0, 0), H - 1);
    const int cy1 = min(max(y1, 0), H - 1);

    const float w00 = (1.0f - wxf) * (1.0f - wyf) * vx0 * vy0;
    const float w01 = wxf * (1.0f - wyf) * vx1 * vy0;
    const float w10 = (1.0f - wxf) * wyf * vx0 * vy1;
    const float w11 = wxf * wyf * vx1 * vy1;

    // paired-tap selection (shared across rows and channels):
    // A = float2 at qa = cx0 & ~1 : contains cx0 (x if even, y if odd),
    //     and contains cx1 iff (cx0 even && cx1 == cx0+1).
    // B = float2 at qb = cx1 & ~1 : loaded only when A doesn't cover cx1.
    const int qa = cx0 & ~1;
    const int qb = cx1 & ~1;
    const bool lo0   = (cx0 == qa);               // cx0 even -> v0 = A.x
    const bool needB = !(lo0 && (cx1 == cx0 + 1)); // A covers v1 otherwise
    const bool lo1   = (cx1 == qb);               // v1 = B.x : B.y (when needB)

    const int rowA0 = cy0 * W + qa;
    const int rowA1 = cy1 * W + qa;
    const int rowB0 = cy0 * W + qb;
    const int rowB1 = cy1 * W + qb;

    const float* __restrict__ sb = src + (size_t)b * C * H * W;
    float* __restrict__ ob = out_trans + (size_t)b * C * H * W;

#pragma unroll
    for (int ch = 0; ch < C; ch++) {
        const float* __restrict__ img = sb + (size_t)ch * (H * W);

        const float2 A0 = __ldg(reinterpret_cast<const float2*>(img + rowA0));
        const float2 A1 = __ldg(reinterpret_cast<const float2*>(img + rowA1));

        float2 B0 = A0, B1 = A1;          // when !needB, v1 comes from A.y
        if (needB) {
            B0 = __ldg(reinterpret_cast<const float2*>(img + rowB0));
            B1 = __ldg(reinterpret_cast<const float2*>(img + rowB1));
        }

        const float v00 = lo0 ? A0.x : A0.y;
        const float v10 = lo0 ? A1.x : A1.y;
        const float v01 = needB ? (lo1 ? B0.x : B0.y) : A0.y;
        const float v11 = needB ? (lo1 ? B1.x : B1.y) : A1.y;

        const float r = fmaf(v00, w00, fmaf(v01, w01, fmaf(v10, w10, v11 * w11)));
        __stcs(&ob[(size_t)ch * (H * W) + pix], r);
    }
}

extern "C" void kernel_launch(void* const* d_in, const int* in_sizes, int n_in,
                              void* d_out, int out_size) {
    const float* src = (const float*)d_in[0];
    const float* fc2 = (const float*)d_in[1];
    float* out = (float*)d_out;

    // output layout: transformed | mat | inv_mat | grid | inv_grid
    const size_t n_trans = (size_t)B * C * H * W;          // 33,554,432
    const size_t n_mat = (size_t)B * 9;                    // 288
    const size_t n_grid = (size_t)B * H * W * 2;           // 16,777,216

    float* out_trans = out;
    float* out_mat   = out + n_trans;
    float* out_inv   = out_mat + n_mat;
    float* out_grid  = out_inv + n_mat;
    float* out_igrid = out_grid + n_grid;

    dim3 grid(W / 32, H / 8, B);
    fused_affine_kernel<<<grid, 256>>>(src, fc2, out_trans, out_mat, out_inv,
                                       out_grid, out_igrid);
}

// round 8
// speedup vs baseline: 4.6020x; 1.3123x over previous
#include <cuda_runtime.h>
#include <math.h>

#define PI_F 3.14159265358979323846f

static const int B = 32, C = 4, H = 512, W = 512;

__device__ __forceinline__ float clampf_(float v, float lo, float hi) {
    return fminf(fmaxf(v, lo), hi);
}

// ---------------------------------------------------------------------------
// Fused kernel (exact R3 memory ops) + per-batch adaptive warp-tile shape.
//  - per-thread recompute of fwd/inv affine matrices from fc2 (fp32)
//  - grid/inv_grid float2 writes; mat/inv_mat from one block
//  - scalar bilinear gathers (4 taps x 4 channels)
//  - lane->pixel mapping chosen per batch among TWxTH in
//    {32x1, 16x2, 8x4, 4x8} to minimize estimated L1 lines of the warp's
//    rotated source footprint (matrix is block-uniform => uniform branch).
// Block tile fixed at 32x8 pixels.
// ---------------------------------------------------------------------------
__global__ __launch_bounds__(256)
void fused_affine_kernel(const float* __restrict__ src,
                         const float* __restrict__ fc2,
                         float* __restrict__ out_trans,
                         float* __restrict__ out_mat,
                         float* __restrict__ out_inv,
                         float* __restrict__ out_grid,
                         float* __restrict__ out_invgrid) {
    const int b = blockIdx.z;

    // --- rebuild matrices in registers (uniform across block) ---
    const float* __restrict__ f = fc2 + b * 7;
    float f0 = __ldg(&f[0]), f1 = __ldg(&f[1]), f2 = __ldg(&f[2]);
    float f3 = __ldg(&f[3]), f4 = __ldg(&f[4]), f5 = __ldg(&f[5]);
    float f6 = __ldg(&f[6]);

    const float theta = clampf_(f0 * 0.3f, -1.f, 1.f) * PI_F;
    const float sx = clampf_(f1 * 0.3f + 1.0f, 0.f, 5.f);
    const float sy = clampf_(f2 * 0.3f + 1.0f, 0.f, 5.f);
    const float tx = f3 * 0.3f;
    const float ty = f4 * 0.3f;
    const float shxy = clampf_(f5 * 0.3f, -1.f, 1.f) * PI_F;
    const float shyx = clampf_(f6 * 0.3f, -1.f, 1.f) * PI_F;

    const float c = cosf(theta), s = sinf(theta);
    const float a  = fmaf(shxy * sy, s, sx * c);
    const float bb = fmaf(shxy * sy, c, -sx * s);
    const float d  = fmaf(shyx * sx, c, sy * s);
    const float e  = fmaf(-shyx * sx, s, sy * c);

    const float det = fmaf(a, e, -bb * d);
    const float rdet = 1.0f / det;
    const float ia  = e * rdet;
    const float ib  = -bb * rdet;
    const float itx = fmaf(bb, ty, -e * tx) * rdet;
    const float id  = -d * rdet;
    const float ie  = a * rdet;
    const float ity = fmaf(d, tx, -a * ty) * rdet;

    if (blockIdx.x == 0 && blockIdx.y == 0 && threadIdx.x == 0) {
        float* om = out_mat + b * 9;
        om[0] = a;  om[1] = bb; om[2] = tx;
        om[3] = d;  om[4] = e;  om[5] = ty;
        om[6] = 0.f; om[7] = 0.f; om[8] = 1.f;
        float* oi = out_inv + b * 9;
        oi[0] = ia; oi[1] = ib; oi[2] = itx;
        oi[3] = id; oi[4] = ie; oi[5] = ity;
        oi[6] = 0.f; oi[7] = 0.f; oi[8] = 1.f;
    }

    // --- per-batch warp-tile shape selection (uniform) ---
    const float fa = fabsf(a), fb = fabsf(bb), fd = fabsf(d), fe = fabsf(e);
    int best_twlog = 3;            // default 8x4 (R3 behavior)
    float best_cost = 3.4e38f;
#pragma unroll
    for (int tl = 2; tl <= 5; tl++) {
        const float TWf = (float)(1 << tl);
        const float THf = (float)(32 >> tl);
        const float Sxs = fa * (TWf - 1.0f) + fb * (THf - 1.0f);  // src x span (px)
        const float Sys = fd * (TWf - 1.0f) + fe * (THf - 1.0f);  // src y span (px)
        // gathers: 16 instr, each ~ rows * lines-per-row
        const float g = 16.0f * (Sys + 2.0f) * (Sxs * 0.03125f + 1.09f);
        // stores: trans (4 instr ~ TH line-segments), grid (2 instr, 8B/px)
        const float st = 4.0f * THf + 2.0f * THf * fmaxf(1.0f, TWf * 0.0625f);
        const float cost = g + st;
        if (cost < best_cost) { best_cost = cost; best_twlog = tl; }
    }
    const int twlog = best_twlog;
    const int TW = 1 << twlog;            // warp tile width
    const int wxlog = 5 - twlog;          // log2(warps across block x)

    // --- pixel coordinates under adaptive mapping; block tile fixed 32x8 ---
    const int tid = threadIdx.x;
    const int lane = tid & 31;
    const int warp = tid >> 5;
    const int lx = lane & (TW - 1);
    const int ly = lane >> twlog;
    const int wpx = warp & ((1 << wxlog) - 1);
    const int wpy = warp >> wxlog;

    const int W0 = blockIdx.x * 32;
    const int H0 = blockIdx.y * 8;
    const int w = W0 + wpx * TW + lx;
    const int h = H0 + wpy * (32 >> twlog) + ly;
    const int pix = h * W + w;

    const float x = (2.0f * (float)w + 1.0f) * (1.0f / (float)W) - 1.0f;
    const float y = (2.0f * (float)h + 1.0f) * (1.0f / (float)H) - 1.0f;

    const float gx = fmaf(a, x, fmaf(bb, y, tx));
    const float gy = fmaf(d, x, fmaf(e, y, ty));
    const float igx = fmaf(ia, x, fmaf(ib, y, itx));
    const float igy = fmaf(id, x, fmaf(ie, y, ity));

    const size_t gidx = (size_t)b * (H * W) + (size_t)pix;
    reinterpret_cast<float2*>(out_grid)[gidx]    = make_float2(gx, gy);
    reinterpret_cast<float2*>(out_invgrid)[gidx] = make_float2(igx, igy);

    // --- bilinear sample with zero padding (exact R3) ---
    const float ixf = ((gx + 1.0f) * (float)W - 1.0f) * 0.5f;
    const float iyf = ((gy + 1.0f) * (float)H - 1.0f) * 0.5f;
    const float x0f = floorf(ixf);
    const float y0f = floorf(iyf);
    const float wxf = ixf - x0f;
    const float wyf = iyf - y0f;
    const int x0 = (int)x0f;
    const int y0 = (int)y0f;
    const int x1 = x0 + 1;
    const int y1 = y0 + 1;

    const float vx0 = (x0 >= 0 && x0 < W) ? 1.0f : 0.0f;
    const float vx1 = (x1 >= 0 && x1 < W) ? 1.0f : 0.0f;
    const float vy0 = (y0 >= 0 && y0 < H) ? 1.0f : 0.0f;
    const float vy1 = (y1 >= 0 && y1 < H) ? 1.0f : 0.0f;

    const int cx0 = min(max(x0, 0), W - 1);
    const int cx1 = min(max(x1, 0), W - 1);
    const int cy0 = min(max(y0, 0), H - 1);
    const int cy1 = min(max(y1, 0), H - 1);

    const float w00 = (1.0f - wxf) * (1.0f - wyf) * vx0 * vy0;
    const float w01 = wxf * (1.0f - wyf) * vx1 * vy0;
    const float w10 = (1.0f - wxf) * wyf * vx0 * vy1;
    const float w11 = wxf * wyf * vx1 * vy1;

    const int off00 = cy0 * W + cx0;
    const int off01 = cy0 * W + cx1;
    const int off10 = cy1 * W + cx0;
    const int off11 = cy1 * W + cx1;

    const float* __restrict__ sb = src + (size_t)b * C * H * W;
    float* __restrict__ ob = out_trans + (size_t)b * C * H * W;

#pragma unroll
    for (int ch = 0; ch < C; ch++) {
        const float* __restrict__ img = sb + (size_t)ch * (H * W);
        float v00 = __ldg(&img[off00]);
        float v01 = __ldg(&img[off01]);
        float v10 = __ldg(&img[off10]);
        float v11 = __ldg(&img[off11]);
        float r = fmaf(v00, w00, fmaf(v01, w01, fmaf(v10, w10, v11 * w11)));
        ob[(size_t)ch * (H * W) + pix] = r;
    }
}

extern "C" void kernel_launch(void* const* d_in, const int* in_sizes, int n_in,
                              void* d_out, int out_size) {
    const float* src = (const float*)d_in[0];
    const float* fc2 = (const float*)d_in[1];
    float* out = (float*)d_out;

    // output layout: transformed | mat | inv_mat | grid | inv_grid
    const size_t n_trans = (size_t)B * C * H * W;          // 33,554,432
    const size_t n_mat = (size_t)B * 9;                    // 288
    const size_t n_grid = (size_t)B * H * W * 2;           // 16,777,216

    float* out_trans = out;
    float* out_mat   = out + n_trans;
    float* out_inv   = out_mat + n_mat;
    float* out_grid  = out_inv + n_mat;
    float* out_igrid = out_grid + n_grid;

    dim3 grid(W / 32, H / 8, B);
    fused_affine_kernel<<<grid, 256>>>(src, fc2, out_trans, out_mat, out_inv,
                                       out_grid, out_igrid);
}

// round 9
// speedup vs baseline: 4.6815x; 1.0173x over previous
#include <cuda_runtime.h>
#include <math.h>

#define PI_F 3.14159265358979323846f

static const int B = 32, C = 4, H = 512, W = 512;

__device__ __forceinline__ float clampf_(float v, float lo, float hi) {
    return fminf(fmaxf(v, lo), hi);
}

// ---------------------------------------------------------------------------
// Fused kernel (exact R3 memory pattern) + deep-MLP gather batching + __stcs:
//  - per-thread recompute of fwd/inv affine matrices from fc2 (fp32)
//  - grid/inv_grid float2 streaming stores; mat/inv_mat from one block
//  - all 16 scalar bilinear gathers issued before any FMA (register budget
//    relaxed via __launch_bounds__(256, 6) so ptxas can keep them in flight)
//  - streaming stores keep src L2-resident
// Warp tile: 8 wide x 4 tall; block tile 32x8.
// ---------------------------------------------------------------------------
__global__ __launch_bounds__(256, 6)
void fused_affine_kernel(const float* __restrict__ src,
                         const float* __restrict__ fc2,
                         float* __restrict__ out_trans,
                         float* __restrict__ out_mat,
                         float* __restrict__ out_inv,
                         float* __restrict__ out_grid,
                         float* __restrict__ out_invgrid) {
    const int b = blockIdx.z;

    // --- rebuild matrices in registers (uniform across block) ---
    const float* __restrict__ f = fc2 + b * 7;
    float f0 = __ldg(&f[0]), f1 = __ldg(&f[1]), f2 = __ldg(&f[2]);
    float f3 = __ldg(&f[3]), f4 = __ldg(&f[4]), f5 = __ldg(&f[5]);
    float f6 = __ldg(&f[6]);

    const float theta = clampf_(f0 * 0.3f, -1.f, 1.f) * PI_F;
    const float sx = clampf_(f1 * 0.3f + 1.0f, 0.f, 5.f);
    const float sy = clampf_(f2 * 0.3f + 1.0f, 0.f, 5.f);
    const float tx = f3 * 0.3f;
    const float ty = f4 * 0.3f;
    const float shxy = clampf_(f5 * 0.3f, -1.f, 1.f) * PI_F;
    const float shyx = clampf_(f6 * 0.3f, -1.f, 1.f) * PI_F;

    const float c = cosf(theta), s = sinf(theta);
    const float a  = fmaf(shxy * sy, s, sx * c);
    const float bb = fmaf(shxy * sy, c, -sx * s);
    const float d  = fmaf(shyx * sx, c, sy * s);
    const float e  = fmaf(-shyx * sx, s, sy * c);

    const float det = fmaf(a, e, -bb * d);
    const float rdet = 1.0f / det;
    const float ia  = e * rdet;
    const float ib  = -bb * rdet;
    const float itx = fmaf(bb, ty, -e * tx) * rdet;
    const float id  = -d * rdet;
    const float ie  = a * rdet;
    const float ity = fmaf(d, tx, -a * ty) * rdet;

    if (blockIdx.x == 0 && blockIdx.y == 0 && threadIdx.x == 0) {
        float* om = out_mat + b * 9;
        om[0] = a;  om[1] = bb; om[2] = tx;
        om[3] = d;  om[4] = e;  om[5] = ty;
        om[6] = 0.f; om[7] = 0.f; om[8] = 1.f;
        float* oi = out_inv + b * 9;
        oi[0] = ia; oi[1] = ib; oi[2] = itx;
        oi[3] = id; oi[4] = ie; oi[5] = ity;
        oi[6] = 0.f; oi[7] = 0.f; oi[8] = 1.f;
    }

    // --- pixel coordinates: 8x4 warp tile, 32x8 block tile ---
    const int tid = threadIdx.x;
    const int lane = tid & 31;
    const int warp = tid >> 5;
    const int lx = lane & 7;
    const int ly = lane >> 3;
    const int wx = warp & 3;
    const int wy = warp >> 2;

    const int w = blockIdx.x * 32 + wx * 8 + lx;
    const int h = blockIdx.y * 8 + wy * 4 + ly;
    const int pix = h * W + w;

    const float x = (2.0f * (float)w + 1.0f) * (1.0f / (float)W) - 1.0f;
    const float y = (2.0f * (float)h + 1.0f) * (1.0f / (float)H) - 1.0f;

    const float gx = fmaf(a, x, fmaf(bb, y, tx));
    const float gy = fmaf(d, x, fmaf(e, y, ty));
    const float igx = fmaf(ia, x, fmaf(ib, y, itx));
    const float igy = fmaf(id, x, fmaf(ie, y, ity));

    const size_t gidx = (size_t)b * (H * W) + (size_t)pix;
    __stcs(reinterpret_cast<float2*>(out_grid) + gidx,    make_float2(gx, gy));
    __stcs(reinterpret_cast<float2*>(out_invgrid) + gidx, make_float2(igx, igy));

    // --- bilinear sample with zero padding (R3 pattern, batched loads) ---
    const float ixf = ((gx + 1.0f) * (float)W - 1.0f) * 0.5f;
    const float iyf = ((gy + 1.0f) * (float)H - 1.0f) * 0.5f;
    const float x0f = floorf(ixf);
    const float y0f = floorf(iyf);
    const float wxf = ixf - x0f;
    const float wyf = iyf - y0f;
    const int x0 = (int)x0f;
    const int y0 = (int)y0f;
    const int x1 = x0 + 1;
    const int y1 = y0 + 1;

    const float vx0 = (x0 >= 0 && x0 < W) ? 1.0f : 0.0f;
    const float vx1 = (x1 >= 0 && x1 < W) ? 1.0f : 0.0f;
    const float vy0 = (y0 >= 0 && y0 < H) ? 1.0f : 0.0f;
    const float vy1 = (y1 >= 0 && y1 < H) ? 1.0f : 0.0f;

    const int cx0 = min(max(x0, 0), W - 1);
    const int cx1 = min(max(x1, 0), W - 1);
    const int cy0 = min(max(y0, 0), H - 1);
    const int cy1 = min(max(y1, 0), H - 1);

    const float w00 = (1.0f - wxf) * (1.0f - wyf) * vx0 * vy0;
    const float w01 = wxf * (1.0f - wyf) * vx1 * vy0;
    const float w10 = (1.0f - wxf) * wyf * vx0 * vy1;
    const float w11 = wxf * wyf * vx1 * vy1;

    const int off00 = cy0 * W + cx0;
    const int off01 = cy0 * W + cx1;
    const int off10 = cy1 * W + cx0;
    const int off11 = cy1 * W + cx1;

    const float* __restrict__ sb = src + (size_t)b * C * H * W;
    float* __restrict__ ob = out_trans + (size_t)b * C * H * W;

    // issue all 16 gathers before any use -> deep MLP
    float v00[C], v01[C], v10[C], v11[C];
#pragma unroll
    for (int ch = 0; ch < C; ch++) {
        const float* __restrict__ img = sb + (size_t)ch * (H * W);
        v00[ch] = __ldg(&img[off00]);
        v01[ch] = __ldg(&img[off01]);
        v10[ch] = __ldg(&img[off10]);
        v11[ch] = __ldg(&img[off11]);
    }
#pragma unroll
    for (int ch = 0; ch < C; ch++) {
        const float r = fmaf(v00[ch], w00,
                        fmaf(v01[ch], w01,
                        fmaf(v10[ch], w10, v11[ch] * w11)));
        __stcs(&ob[(size_t)ch * (H * W) + pix], r);
    }
}

extern "C" void kernel_launch(void* const* d_in, const int* in_sizes, int n_in,
                              void* d_out, int out_size) {
    const float* src = (const float*)d_in[0];
    const float* fc2 = (const float*)d_in[1];
    float* out = (float*)d_out;

    // output layout: transformed | mat | inv_mat | grid | inv_grid
    const size_t n_trans = (size_t)B * C * H * W;          // 33,554,432
    const size_t n_mat = (size_t)B * 9;                    // 288
    const size_t n_grid = (size_t)B * H * W * 2;           // 16,777,216

    float* out_trans = out;
    float* out_mat   = out + n_trans;
    float* out_inv   = out_mat + n_mat;
    float* out_grid  = out_inv + n_mat;
    float* out_igrid = out_grid + n_grid;

    dim3 grid(W / 32, H / 8, B);
    fused_affine_kernel<<<grid, 256>>>(src, fc2, out_trans, out_mat, out_inv,
                                       out_grid, out_igrid);
}

// round 10
// speedup vs baseline: 4.7491x; 1.0144x over previous
#include <cuda_runtime.h>
#include <math.h>

#define PI_F 3.14159265358979323846f

static const int B = 32, C = 4, H = 512, W = 512;

__device__ __forceinline__ float clampf_(float v, float lo, float hi) {
    return fminf(fmaxf(v, lo), hi);
}

// ---------------------------------------------------------------------------
// R3 structure exactly (the measured local optimum), with one delta:
// __stcs (evict-first streaming) on all large output stores so the src
// working set stays L2-resident for the gathers.
//  - per-thread recompute of fwd/inv affine matrices from fc2 (fp32)
//  - grid/inv_grid float2 streaming stores; mat/inv_mat from one block
//  - 16 scalar bilinear gathers (4 taps x 4 channels), channel-serial
// Warp tile: 8 wide x 4 tall; block tile 32x8.
// ---------------------------------------------------------------------------
__global__ __launch_bounds__(256)
void fused_affine_kernel(const float* __restrict__ src,
                         const float* __restrict__ fc2,
                         float* __restrict__ out_trans,
                         float* __restrict__ out_mat,
                         float* __restrict__ out_inv,
                         float* __restrict__ out_grid,
                         float* __restrict__ out_invgrid) {
    const int b = blockIdx.z;

    // --- rebuild matrices in registers (uniform across block) ---
    const float* __restrict__ f = fc2 + b * 7;
    float f0 = __ldg(&f[0]), f1 = __ldg(&f[1]), f2 = __ldg(&f[2]);
    float f3 = __ldg(&f[3]), f4 = __ldg(&f[4]), f5 = __ldg(&f[5]);
    float f6 = __ldg(&f[6]);

    const float theta = clampf_(f0 * 0.3f, -1.f, 1.f) * PI_F;
    const float sx = clampf_(f1 * 0.3f + 1.0f, 0.f, 5.f);
    const float sy = clampf_(f2 * 0.3f + 1.0f, 0.f, 5.f);
    const float tx = f3 * 0.3f;
    const float ty = f4 * 0.3f;
    const float shxy = clampf_(f5 * 0.3f, -1.f, 1.f) * PI_F;
    const float shyx = clampf_(f6 * 0.3f, -1.f, 1.f) * PI_F;

    const float c = cosf(theta), s = sinf(theta);
    const float a  = fmaf(shxy * sy, s, sx * c);
    const float bb = fmaf(shxy * sy, c, -sx * s);
    const float d  = fmaf(shyx * sx, c, sy * s);
    const float e  = fmaf(-shyx * sx, s, sy * c);

    const float det = fmaf(a, e, -bb * d);
    const float rdet = 1.0f / det;
    const float ia  = e * rdet;
    const float ib  = -bb * rdet;
    const float itx = fmaf(bb, ty, -e * tx) * rdet;
    const float id  = -d * rdet;
    const float ie  = a * rdet;
    const float ity = fmaf(d, tx, -a * ty) * rdet;

    if (blockIdx.x == 0 && blockIdx.y == 0 && threadIdx.x == 0) {
        float* om = out_mat + b * 9;
        om[0] = a;  om[1] = bb; om[2] = tx;
        om[3] = d;  om[4] = e;  om[5] = ty;
        om[6] = 0.f; om[7] = 0.f; om[8] = 1.f;
        float* oi = out_inv + b * 9;
        oi[0] = ia; oi[1] = ib; oi[2] = itx;
        oi[3] = id; oi[4] = ie; oi[5] = ity;
        oi[6] = 0.f; oi[7] = 0.f; oi[8] = 1.f;
    }

    // --- pixel coordinates: 8x4 warp tile, 32x8 block tile ---
    const int tid = threadIdx.x;
    const int lane = tid & 31;
    const int warp = tid >> 5;
    const int lx = lane & 7;
    const int ly = lane >> 3;
    const int wx = warp & 3;
    const int wy = warp >> 2;

    const int w = blockIdx.x * 32 + wx * 8 + lx;
    const int h = blockIdx.y * 8 + wy * 4 + ly;
    const int pix = h * W + w;

    const float x = (2.0f * (float)w + 1.0f) * (1.0f / (float)W) - 1.0f;
    const float y = (2.0f * (float)h + 1.0f) * (1.0f / (float)H) - 1.0f;

    const float gx = fmaf(a, x, fmaf(bb, y, tx));
    const float gy = fmaf(d, x, fmaf(e, y, ty));
    const float igx = fmaf(ia, x, fmaf(ib, y, itx));
    const float igy = fmaf(id, x, fmaf(ie, y, ity));

    const size_t gidx = (size_t)b * (H * W) + (size_t)pix;
    __stcs(reinterpret_cast<float2*>(out_grid) + gidx,    make_float2(gx, gy));
    __stcs(reinterpret_cast<float2*>(out_invgrid) + gidx, make_float2(igx, igy));

    // --- bilinear sample with zero padding (exact R3 pattern) ---
    const float ixf = ((gx + 1.0f) * (float)W - 1.0f) * 0.5f;
    const float iyf = ((gy + 1.0f) * (float)H - 1.0f) * 0.5f;
    const float x0f = floorf(ixf);
    const float y0f = floorf(iyf);
    const float wxf = ixf - x0f;
    const float wyf = iyf - y0f;
    const int x0 = (int)x0f;
    const int y0 = (int)y0f;
    const int x1 = x0 + 1;
    const int y1 = y0 + 1;

    const float vx0 = (x0 >= 0 && x0 < W) ? 1.0f : 0.0f;
    const float vx1 = (x1 >= 0 && x1 < W) ? 1.0f : 0.0f;
    const float vy0 = (y0 >= 0 && y0 < H) ? 1.0f : 0.0f;
    const float vy1 = (y1 >= 0 && y1 < H) ? 1.0f : 0.0f;

    const int cx0 = min(max(x0, 0), W - 1);
    const int cx1 = min(max(x1, 0), W - 1);
    const int cy0 = min(max(y0, 0), H - 1);
    const int cy1 = min(max(y1, 0), H - 1);

    const float w00 = (1.0f - wxf) * (1.0f - wyf) * vx0 * vy0;
    const float w01 = wxf * (1.0f - wyf) * vx1 * vy0;
    const float w10 = (1.0f - wxf) * wyf * vx0 * vy1;
    const float w11 = wxf * wyf * vx1 * vy1;

    const int off00 = cy0 * W + cx0;
    const int off01 = cy0 * W + cx1;
    const int off10 = cy1 * W + cx0;
    const int off11 = cy1 * W + cx1;

    const float* __restrict__ sb = src + (size_t)b * C * H * W;
    float* __restrict__ ob = out_trans + (size_t)b * C * H * W;

#pragma unroll
    for (int ch = 0; ch < C; ch++) {
        const float* __restrict__ img = sb + (size_t)ch * (H * W);
        float v00 = __ldg(&img[off00]);
        float v01 = __ldg(&img[off01]);
        float v10 = __ldg(&img[off10]);
        float v11 = __ldg(&img[off11]);
        float r = fmaf(v00, w00, fmaf(v01, w01, fmaf(v10, w10, v11 * w11)));
        __stcs(&ob[(size_t)ch * (H * W) + pix], r);
    }
}

extern "C" void kernel_launch(void* const* d_in, const int* in_sizes, int n_in,
                              void* d_out, int out_size) {
    const float* src = (const float*)d_in[0];
    const float* fc2 = (const float*)d_in[1];
    float* out = (float*)d_out;

    // output layout: transformed | mat | inv_mat | grid | inv_grid
    const size_t n_trans = (size_t)B * C * H * W;          // 33,554,432
    const size_t n_mat = (size_t)B * 9;                    // 288
    const size_t n_grid = (size_t)B * H * W * 2;           // 16,777,216

    float* out_trans = out;
    float* out_mat   = out + n_trans;
    float* out_inv   = out_mat + n_mat;
    float* out_grid  = out_inv + n_mat;
    float* out_igrid = out_grid + n_grid;

    dim3 grid(W / 32, H / 8, B);
    fused_affine_kernel<<<grid, 256>>>(src, fc2, out_trans, out_mat, out_inv,
                                       out_grid, out_igrid);
}